// round 15
// baseline (speedup 1.0000x reference)
#include <cuda_runtime.h>
#include <cuda_fp16.h>
#include <cstdint>

#define NB      2
#define SEQ     2048
#define DMODEL  1024
#define HEADS   16
#define HD      64
#define MTOT    (NB*SEQ)        // 4096
#define N_QKV   (3*DMODEL)      // 3072

// Scratch (static device globals -- no allocation anywhere). All fp16.
__device__ __half g_qb[NB*HEADS*SEQ*HD];   // [b,h,s,hd]
__device__ __half g_kb[NB*HEADS*SEQ*HD];   // [b,h,s,hd]
__device__ __half g_vb[NB*HEADS*SEQ*HD];   // [b,h,hd,s]  TRANSPOSED
__device__ __half g_ab[MTOT*DMODEL];       // attention out [m, d]
__device__ __half g_xh[MTOT*DMODEL];       // fp16 x
__device__ __half g_wqh[N_QKV*DMODEL];     // fp16 Wqkv
__device__ __half g_wdh[DMODEL*DMODEL];    // fp16 Wd

// ---------------- helpers ----------------
__device__ __forceinline__ void mma16(float c[4],
                                      unsigned a0, unsigned a1, unsigned a2, unsigned a3,
                                      unsigned b0, unsigned b1) {
    asm volatile(
        "mma.sync.aligned.m16n8k16.row.col.f32.f16.f16.f32 "
        "{%0,%1,%2,%3}, {%4,%5,%6,%7}, {%8,%9}, {%0,%1,%2,%3};\n"
        : "+f"(c[0]), "+f"(c[1]), "+f"(c[2]), "+f"(c[3])
        : "r"(a0), "r"(a1), "r"(a2), "r"(a3), "r"(b0), "r"(b1));
}

__device__ __forceinline__ uint32_t s2u(const void* p) {
    uint32_t a;
    asm("{ .reg .u64 t; cvta.to.shared.u64 t, %1; cvt.u32.u64 %0, t; }"
        : "=r"(a) : "l"(p));
    return a;
}

__device__ __forceinline__ void cpasync16(uint32_t s, const void* g) {
    asm volatile("cp.async.cg.shared.global [%0], [%1], 16;" :: "r"(s), "l"(g));
}
__device__ __forceinline__ void cpcommit() {
    asm volatile("cp.async.commit_group;" ::: "memory");
}
__device__ __forceinline__ void cpwait0() {
    asm volatile("cp.async.wait_group 0;" ::: "memory");
}

__device__ __forceinline__ unsigned pack2(float lo, float hi) {
    __half2 h = __floats2half2_rn(lo, hi);
    return *reinterpret_cast<unsigned*>(&h);
}

// ---------------- convert: x, Wqkv, Wd -> fp16 ----------------
__global__ void convert_kernel(const float* __restrict__ x,
                               const float* __restrict__ wqkv,
                               const float* __restrict__ wd)
{
    const int N1 = MTOT * DMODEL / 4;
    const int N2 = N_QKV * DMODEL / 4;
    const int N3 = DMODEL * DMODEL / 4;
    const int total = N1 + N2 + N3;
    for (int i = blockIdx.x * blockDim.x + threadIdx.x; i < total;
         i += gridDim.x * blockDim.x) {
        const float4* src; __half* dst; int off;
        if (i < N1)           { src = (const float4*)x;    dst = g_xh;  off = i; }
        else if (i < N1 + N2) { src = (const float4*)wqkv; dst = g_wqh; off = i - N1; }
        else                  { src = (const float4*)wd;   dst = g_wdh; off = i - N1 - N2; }
        float4 v = src[off];
        uint2 o;
        o.x = pack2(v.x, v.y);
        o.y = pack2(v.z, v.w);
        *reinterpret_cast<uint2*>(dst + (size_t)off * 4) = o;
    }
}

// ---------------- GEMM: C[M,N] = A[M,K] @ B[N,K]^T + bias ----------------
// fp16 A/B, fp32 accum (m16n8k16). CTA 128x128, 8 warps (2m x 4n), warp tile
// 64x32. KC=64 chunks: stage = 2 sub-tiles per operand, each 128 rows x 32
// halves data at pitch 48 halves (96B -> conflict-free LDS.64 fragments).
// 2-stage cp.async pipeline, ONE __syncthreads per chunk:
//   wait(ch) -> sync -> issue(ch+1) -> compute(ch)
// issue(ch+1) overwrites the stage last read at compute(ch-1); every warp at
// the sync has finished compute(ch-1), so the barrier orders reads vs writes.
#define GEMM_SUB_BYTES   12288                     // 128 x 96B
#define GEMM_STAGE_BYTES (4 * GEMM_SUB_BYTES)      // A0,A1,B0,B1 = 49152
#define GEMM_SMEM_BYTES  (2 * GEMM_STAGE_BYTES)    // 98304, 2 CTAs/SM

template<int MODE>
__global__ __launch_bounds__(256, 2)
void gemm_kernel(const __half* __restrict__ Bw, const float* __restrict__ bias,
                 float* __restrict__ C, int M, int N, int K)
{
    extern __shared__ char gsm[];
    const __half* A = (MODE == 1) ? g_ab : g_xh;
    const __half* B = Bw;

    const uint32_t sbase = s2u(gsm);
    const int tid  = threadIdx.x;
    const int wid  = tid >> 5, lane = tid & 31;
    const int g    = lane >> 2, t = lane & 3;
    const int wm   = (wid >> 2) * 64;   // 2 warps in m
    const int wn   = (wid & 3) * 32;    // 4 warps in n
    const int m0   = blockIdx.y * 128, n0 = blockIdx.x * 128;

    float acc[4][4][4];
#pragma unroll
    for (int i = 0; i < 4; i++)
#pragma unroll
        for (int j = 0; j < 4; j++)
#pragma unroll
            for (int c = 0; c < 4; c++) acc[i][j][c] = 0.f;

    const int NCH = K / 64;             // 16
    const int srow = tid >> 1;          // 0..127
    const int q0   = (tid & 1) * 4;     // first 16B unit (0 or 4) of 8

    // issue chunk ch (64 k) into stage st: 8 cp.async per thread
    auto issue = [&](int ch, int st) {
        const int k0 = ch * 64;
        const uint32_t sb = sbase + (uint32_t)st * GEMM_STAGE_BYTES;
#pragma unroll
        for (int j = 0; j < 4; j++) {
            int q = q0 + j;                         // 0..7
            uint32_t d = (uint32_t)((q >> 2) * GEMM_SUB_BYTES + srow * 96 + (q & 3) * 16);
            cpasync16(sb + d,
                      &A[(size_t)(m0 + srow) * K + k0 + q * 8]);
            cpasync16(sb + 2u * GEMM_SUB_BYTES + d,
                      &B[(size_t)(n0 + srow) * K + k0 + q * 8]);
        }
        cpcommit();
    };

    issue(0, 0);

    for (int ch = 0; ch < NCH; ch++) {
        cpwait0();
        __syncthreads();
        if (ch + 1 < NCH) issue(ch + 1, (ch + 1) & 1);

        const char* St = gsm + (ch & 1) * GEMM_STAGE_BYTES;
#pragma unroll
        for (int kk = 0; kk < 4; kk++) {            // four k16 steps
            const char* As = St + (kk >> 1) * GEMM_SUB_BYTES;
            const char* Bs = St + 2 * GEMM_SUB_BYTES + (kk >> 1) * GEMM_SUB_BYTES;
            const int ko = (kk & 1) * 32;
            unsigned b0[4], b1[4];
#pragma unroll
            for (int nf = 0; nf < 4; nf++) {
                uint2 bv = *reinterpret_cast<const uint2*>(
                    Bs + (wn + nf * 8 + g) * 96 + ko + t * 8);
                b0[nf] = bv.x; b1[nf] = bv.y;
            }
#pragma unroll
            for (int mf = 0; mf < 4; mf++) {
                int r0 = wm + mf * 16 + g;
                uint2 a0v = *reinterpret_cast<const uint2*>(
                    As + r0 * 96 + ko + t * 8);
                uint2 a1v = *reinterpret_cast<const uint2*>(
                    As + (r0 + 8) * 96 + ko + t * 8);
#pragma unroll
                for (int nf = 0; nf < 4; nf++)
                    mma16(acc[mf][nf], a0v.x, a1v.x, a0v.y, a1v.y,
                          b0[nf], b1[nf]);
            }
        }
        // no trailing barrier: next iteration's sync provides the ordering
    }

#pragma unroll
    for (int mf = 0; mf < 4; mf++)
#pragma unroll
        for (int nf = 0; nf < 4; nf++)
#pragma unroll
            for (int c = 0; c < 4; c++) {
                int row = m0 + wm + mf * 16 + g + ((c >= 2) ? 8 : 0);
                int col = n0 + wn + nf * 8 + 2 * t + (c & 1);
                float v = acc[mf][nf][c] + bias[col];
                if (MODE == 0) {
                    int part = col >> 10, nn = col & 1023;
                    int hh = nn >> 6, e = nn & 63;
                    int bb = row >> 11, sq = row & 2047;
                    __half hv = __float2half_rn(v);
                    if (part == 0)
                        g_qb[(((size_t)(bb * HEADS + hh)) * SEQ + sq) * HD + e] = hv;
                    else if (part == 1)
                        g_kb[(((size_t)(bb * HEADS + hh)) * SEQ + sq) * HD + e] = hv;
                    else  // V stored TRANSPOSED [b,h,hd,s]
                        g_vb[(((size_t)(bb * HEADS + hh)) * HD + e) * SEQ + sq] = hv;
                } else {
                    C[(size_t)row * N + col] = v;
                }
            }
}

// ---------------- Flash attention (fp16 mma) ----------------
// 256 threads (8 warps), 128-row q tile. CTA x=p handles tiles {p, 15-p}.
// K tile [64 kv][64 hd], V^T tile [64 hd][64 kv]: pitch 80 halves (160B,
// conflict-free LDS.64). P fp16 [128][pitch 80]. Single-barrier pipeline:
//   wait(j) -> sync -> issue(j+1) -> compute(j)
// Byte layout: K stage s at s*10240; V^T stage s at 20480+s*10240; P at 40960.
#define FA_SMEM_BYTES (40960 + 20480)   // 61440

__global__ __launch_bounds__(256)
void fa_kernel(const int* __restrict__ maskp)
{
    extern __shared__ char fsm[];
    char* Ps = fsm + 40960;

    const int tid = threadIdx.x, wid = tid >> 5, lane = tid & 31;
    const int g = lane >> 2, t = lane & 3;
    const int bh = blockIdx.y;
    const int causal = (maskp[0] != 0);

    const __half* kp  = g_kb + (size_t)bh * SEQ * HD;   // [s][hd]
    const __half* vtp = g_vb + (size_t)bh * HD * SEQ;   // [hd][s]
    const uint32_t fbase = s2u(fsm);
    const int wr = wid * 16;
    const int row0 = wr + g, row1 = wr + g + 8;
    const int b = bh >> 4, h = bh & 15;

    const int srow = (tid >> 2) & 63;
    const int sq0  = (tid & 3) * 2;

    for (int sub = 0; sub < 2; sub++) {
        const int Q = sub ? (15 - (int)blockIdx.x) : (int)blockIdx.x;
        const __half* qp = g_qb + ((size_t)bh * SEQ + Q * 128) * HD;

        unsigned qf[4][4];
#pragma unroll
        for (int kk = 0; kk < 4; kk++) {
            uint2 x0 = *reinterpret_cast<const uint2*>(&qp[(size_t)row0 * HD + kk * 16 + 4 * t]);
            uint2 x1 = *reinterpret_cast<const uint2*>(&qp[(size_t)row1 * HD + kk * 16 + 4 * t]);
            qf[kk][0] = x0.x; qf[kk][1] = x1.x;
            qf[kk][2] = x0.y; qf[kk][3] = x1.y;
        }

        float of[8][4];
#pragma unroll
        for (int nf = 0; nf < 8; nf++)
#pragma unroll
            for (int c = 0; c < 4; c++) of[nf][c] = 0.f;

        float m0 = -1e30f, m1 = -1e30f, l0 = 0.f, l1 = 0.f;
        const int grow0 = Q * 128 + row0, grow1 = Q * 128 + row1;

        const int jend = causal ? (2 * Q + 2) : (SEQ / 64);

        auto issuekv = [&](int j, int st) {
            const uint32_t kb = fbase + (uint32_t)st * 10240;
            const uint32_t vb = fbase + 20480u + (uint32_t)st * 10240;
#pragma unroll
            for (int i = 0; i < 2; i++) {
                int q = sq0 + i;
                uint32_t dofs = (uint32_t)(srow * 160 + q * 16);
                cpasync16(kb + dofs, &kp[((size_t)j * 64 + srow) * HD + q * 8]);
                cpasync16(vb + dofs, &vtp[(size_t)srow * SEQ + j * 64 + q * 8]);
            }
            cpcommit();
        };

        issuekv(0, 0);

        for (int j = 0; j < jend; j++) {
            cpwait0();
            __syncthreads();
            if (j + 1 < jend) issuekv(j + 1, (j + 1) & 1);

            const int cur = j & 1;
            const char* Ks = fsm + cur * 10240;
            const char* Vt = fsm + 20480 + cur * 10240;

            // S = Q K^T
            float sf[8][4];
#pragma unroll
            for (int nf = 0; nf < 8; nf++)
#pragma unroll
                for (int c = 0; c < 4; c++) sf[nf][c] = 0.f;
#pragma unroll
            for (int kk = 0; kk < 4; kk++) {
#pragma unroll
                for (int nf = 0; nf < 8; nf++) {
                    uint2 bv = *reinterpret_cast<const uint2*>(
                        Ks + (nf * 8 + g) * 160 + kk * 32 + t * 8);
                    mma16(sf[nf], qf[kk][0], qf[kk][1], qf[kk][2], qf[kk][3],
                          bv.x, bv.y);
                }
            }

            // scale + causal mask
            const bool mk = causal && (j >= 2 * Q);
            const int jc = j * 64;
#pragma unroll
            for (int nf = 0; nf < 8; nf++) {
                int c0 = jc + nf * 8 + 2 * t, c1 = c0 + 1;
                sf[nf][0] = (mk && c0 > grow0) ? -1e30f : sf[nf][0] * 0.125f;
                sf[nf][1] = (mk && c1 > grow0) ? -1e30f : sf[nf][1] * 0.125f;
                sf[nf][2] = (mk && c0 > grow1) ? -1e30f : sf[nf][2] * 0.125f;
                sf[nf][3] = (mk && c1 > grow1) ? -1e30f : sf[nf][3] * 0.125f;
            }

            // register softmax across the t-quad
            float mx0 = -1e30f, mx1 = -1e30f;
#pragma unroll
            for (int nf = 0; nf < 8; nf++) {
                mx0 = fmaxf(mx0, fmaxf(sf[nf][0], sf[nf][1]));
                mx1 = fmaxf(mx1, fmaxf(sf[nf][2], sf[nf][3]));
            }
            mx0 = fmaxf(mx0, __shfl_xor_sync(0xffffffffu, mx0, 1));
            mx0 = fmaxf(mx0, __shfl_xor_sync(0xffffffffu, mx0, 2));
            mx1 = fmaxf(mx1, __shfl_xor_sync(0xffffffffu, mx1, 1));
            mx1 = fmaxf(mx1, __shfl_xor_sync(0xffffffffu, mx1, 2));
            const float nm0 = fmaxf(m0, mx0), nm1 = fmaxf(m1, mx1);

            float sum0 = 0.f, sum1 = 0.f;
#pragma unroll
            for (int nf = 0; nf < 8; nf++) {
                sf[nf][0] = __expf(sf[nf][0] - nm0);
                sf[nf][1] = __expf(sf[nf][1] - nm0);
                sf[nf][2] = __expf(sf[nf][2] - nm1);
                sf[nf][3] = __expf(sf[nf][3] - nm1);
                sum0 += sf[nf][0] + sf[nf][1];
                sum1 += sf[nf][2] + sf[nf][3];
            }
            sum0 += __shfl_xor_sync(0xffffffffu, sum0, 1);
            sum0 += __shfl_xor_sync(0xffffffffu, sum0, 2);
            sum1 += __shfl_xor_sync(0xffffffffu, sum1, 1);
            sum1 += __shfl_xor_sync(0xffffffffu, sum1, 2);

            const float sc0 = __expf(m0 - nm0), sc1 = __expf(m1 - nm1);
            l0 = l0 * sc0 + sum0; l1 = l1 * sc1 + sum1;
            m0 = nm0; m1 = nm1;

            // P (fp16) to its own buffer (warp-local rows)
#pragma unroll
            for (int nf = 0; nf < 8; nf++) {
                *reinterpret_cast<unsigned*>(Ps + row0 * 160 + nf * 16 + t * 4)
                    = pack2(sf[nf][0], sf[nf][1]);
                *reinterpret_cast<unsigned*>(Ps + row1 * 160 + nf * 16 + t * 4)
                    = pack2(sf[nf][2], sf[nf][3]);
            }
            __syncwarp();

            // rescale O, then O += P V
#pragma unroll
            for (int nf = 0; nf < 8; nf++) {
                of[nf][0] *= sc0; of[nf][1] *= sc0; of[nf][2] *= sc1; of[nf][3] *= sc1;
            }
#pragma unroll
            for (int kk = 0; kk < 4; kk++) {
                uint2 p0 = *reinterpret_cast<const uint2*>(Ps + row0 * 160 + kk * 32 + t * 8);
                uint2 p1 = *reinterpret_cast<const uint2*>(Ps + row1 * 160 + kk * 32 + t * 8);
#pragma unroll
                for (int nf = 0; nf < 8; nf++) {
                    uint2 bv = *reinterpret_cast<const uint2*>(
                        Vt + (nf * 8 + g) * 160 + kk * 32 + t * 8);
                    mma16(of[nf], p0.x, p1.x, p0.y, p1.y, bv.x, bv.y);
                }
            }
            // no trailing barrier: next iteration's sync provides ordering
        }
        __syncthreads();   // protect smem before next sub's prologue issue

        // normalize and write g_ab fp16 [b, s, h, hd]
        const float il0 = 1.f / l0, il1 = 1.f / l1;
        const int q0 = Q * 128 + row0, q1 = Q * 128 + row1;
#pragma unroll
        for (int nf = 0; nf < 8; nf++) {
            int col = nf * 8 + 2 * t;
            *reinterpret_cast<unsigned*>(
                &g_ab[(((size_t)b * SEQ + q0) * HEADS + h) * HD + col])
                = pack2(of[nf][0] * il0, of[nf][1] * il0);
            *reinterpret_cast<unsigned*>(
                &g_ab[(((size_t)b * SEQ + q1) * HEADS + h) * HD + col])
                = pack2(of[nf][2] * il1, of[nf][3] * il1);
        }
    }
}

// ---------------- launch ----------------
extern "C" void kernel_launch(void* const* d_in, const int* in_sizes, int n_in,
                              void* d_out, int out_size)
{
    const float* x    = (const float*)d_in[0];
    const float* Wqkv = (const float*)d_in[1];
    const float* bqkv = (const float*)d_in[2];
    const float* Wd   = (const float*)d_in[3];
    const float* bd   = (const float*)d_in[4];
    const int*   mask = (const int*)d_in[5];
    float* out = (float*)d_out;

    cudaFuncSetAttribute(gemm_kernel<0>, cudaFuncAttributeMaxDynamicSharedMemorySize, GEMM_SMEM_BYTES);
    cudaFuncSetAttribute(gemm_kernel<1>, cudaFuncAttributeMaxDynamicSharedMemorySize, GEMM_SMEM_BYTES);
    cudaFuncSetAttribute(fa_kernel,      cudaFuncAttributeMaxDynamicSharedMemorySize, FA_SMEM_BYTES);

    static __half* wq_dev = nullptr;
    static __half* wd_dev = nullptr;
    if (!wq_dev) {
        cudaGetSymbolAddress((void**)&wq_dev, g_wqh);
        cudaGetSymbolAddress((void**)&wd_dev, g_wdh);
    }

    convert_kernel<<<1024, 256>>>(x, Wqkv, Wd);

    gemm_kernel<0><<<dim3(N_QKV / 128, MTOT / 128), 256, GEMM_SMEM_BYTES>>>(
        wq_dev, bqkv, nullptr, MTOT, N_QKV, DMODEL);

    fa_kernel<<<dim3(8, NB * HEADS), 256, FA_SMEM_BYTES>>>(mask);

    gemm_kernel<1><<<dim3(DMODEL / 128, MTOT / 128), 256, GEMM_SMEM_BYTES>>>(
        wd_dev, bd, out, MTOT, DMODEL, DMODEL);
}

// round 17
// speedup vs baseline: 1.1708x; 1.1708x over previous
#include <cuda_runtime.h>
#include <cuda_fp16.h>
#include <cstdint>

#define NB      2
#define SEQ     2048
#define DMODEL  1024
#define HEADS   16
#define HD      64
#define MTOT    (NB*SEQ)        // 4096
#define N_QKV   (3*DMODEL)      // 3072

// Scratch (static device globals -- no allocation anywhere). All fp16.
__device__ __half g_qb[NB*HEADS*SEQ*HD];   // [b,h,s,hd]
__device__ __half g_kb[NB*HEADS*SEQ*HD];   // [b,h,s,hd]
__device__ __half g_vb[NB*HEADS*SEQ*HD];   // [b,h,hd,s]  TRANSPOSED
__device__ __half g_ab[MTOT*DMODEL];       // attention out [m, d]
__device__ __half g_xh[MTOT*DMODEL];       // fp16 x
__device__ __half g_wqh[N_QKV*DMODEL];     // fp16 Wqkv
__device__ __half g_wdh[DMODEL*DMODEL];    // fp16 Wd

// ---------------- helpers ----------------
__device__ __forceinline__ void mma16(float c[4],
                                      unsigned a0, unsigned a1, unsigned a2, unsigned a3,
                                      unsigned b0, unsigned b1) {
    asm volatile(
        "mma.sync.aligned.m16n8k16.row.col.f32.f16.f16.f32 "
        "{%0,%1,%2,%3}, {%4,%5,%6,%7}, {%8,%9}, {%0,%1,%2,%3};\n"
        : "+f"(c[0]), "+f"(c[1]), "+f"(c[2]), "+f"(c[3])
        : "r"(a0), "r"(a1), "r"(a2), "r"(a3), "r"(b0), "r"(b1));
}

__device__ __forceinline__ uint32_t s2u(const void* p) {
    uint32_t a;
    asm("{ .reg .u64 t; cvta.to.shared.u64 t, %1; cvt.u32.u64 %0, t; }"
        : "=r"(a) : "l"(p));
    return a;
}

__device__ __forceinline__ void cpasync16(uint32_t s, const void* g) {
    asm volatile("cp.async.cg.shared.global [%0], [%1], 16;" :: "r"(s), "l"(g));
}
__device__ __forceinline__ void cpcommit() {
    asm volatile("cp.async.commit_group;" ::: "memory");
}
__device__ __forceinline__ void cpwait0() {
    asm volatile("cp.async.wait_group 0;" ::: "memory");
}
__device__ __forceinline__ void cpwait1() {
    asm volatile("cp.async.wait_group 1;" ::: "memory");
}

__device__ __forceinline__ unsigned pack2(float lo, float hi) {
    __half2 h = __floats2half2_rn(lo, hi);
    return *reinterpret_cast<unsigned*>(&h);
}

// ---------------- convert: x, Wqkv, Wd -> fp16 ----------------
__global__ void convert_kernel(const float* __restrict__ x,
                               const float* __restrict__ wqkv,
                               const float* __restrict__ wd)
{
    const int N1 = MTOT * DMODEL / 4;
    const int N2 = N_QKV * DMODEL / 4;
    const int N3 = DMODEL * DMODEL / 4;
    const int total = N1 + N2 + N3;
    for (int i = blockIdx.x * blockDim.x + threadIdx.x; i < total;
         i += gridDim.x * blockDim.x) {
        const float4* src; __half* dst; int off;
        if (i < N1)           { src = (const float4*)x;    dst = g_xh;  off = i; }
        else if (i < N1 + N2) { src = (const float4*)wqkv; dst = g_wqh; off = i - N1; }
        else                  { src = (const float4*)wd;   dst = g_wdh; off = i - N1 - N2; }
        float4 v = src[off];
        uint2 o;
        o.x = pack2(v.x, v.y);
        o.y = pack2(v.z, v.w);
        *reinterpret_cast<uint2*>(dst + (size_t)off * 4) = o;
    }
}

// ---------------- GEMM: C[M,N] = A[M,K] @ B[N,K]^T + bias ----------------
// fp16 A/B, fp32 accum via m16n8k16. CTA 128x128, 8 warps (2m x 4n), warp
// tile 64x32. Smem rows: 32 halves data, pitch 48 halves (96B -> conflict-
// free LDS.64 fragments). KC=32, 3-stage cp.async pipeline with ONE barrier
// per chunk:  wait1 -> sync -> issue(ch+2) -> compute(ch).
// issue(ch+2) writes stage (ch+2)%3 = (ch-1)%3, last read at compute(ch-1);
// every warp past the sync has finished compute(ch-1) -> no race, and two
// groups (ch+1, ch+2) stay in flight through each compute phase (depth-2
// latency cover, same as R13).
#define GEMM_STAGE_BYTES (2 * 128 * 96)            // A + B = 24576
#define GEMM_SMEM_BYTES  (3 * GEMM_STAGE_BYTES)    // 73728, 2 CTAs/SM

template<int MODE>
__global__ __launch_bounds__(256, 2)
void gemm_kernel(const __half* __restrict__ Bw, const float* __restrict__ bias,
                 float* __restrict__ C, int M, int N, int K)
{
    extern __shared__ char gsm[];
    const __half* A = (MODE == 1) ? g_ab : g_xh;
    const __half* B = Bw;

    const uint32_t sbase = s2u(gsm);
    const int tid  = threadIdx.x;
    const int wid  = tid >> 5, lane = tid & 31;
    const int g    = lane >> 2, t = lane & 3;
    const int wm   = (wid >> 2) * 64;   // 2 warps in m
    const int wn   = (wid & 3) * 32;    // 4 warps in n
    const int m0   = blockIdx.y * 128, n0 = blockIdx.x * 128;

    const int srow = tid >> 1;                 // 0..127
    float acc[4][4][4];
#pragma unroll
    for (int i = 0; i < 4; i++)
#pragma unroll
        for (int j = 0; j < 4; j++)
#pragma unroll
            for (int c = 0; c < 4; c++) acc[i][j][c] = 0.f;

    const int NCH = K / 32;

    auto issue = [&](int ch, int st) {
        const int k0 = ch * 32;
        const uint32_t sb = sbase + (uint32_t)st * GEMM_STAGE_BYTES;
        const int q0 = (tid & 1) * 2;
#pragma unroll
        for (int j = 0; j < 2; j++) {
            int q = q0 + j;
            cpasync16(sb + (uint32_t)(srow * 96 + q * 16),
                      &A[(size_t)(m0 + srow) * K + k0 + q * 8]);
            cpasync16(sb + 12288u + (uint32_t)(srow * 96 + q * 16),
                      &B[(size_t)(n0 + srow) * K + k0 + q * 8]);
        }
        cpcommit();
    };

    issue(0, 0);
    if (NCH > 1) issue(1, 1);

    for (int ch = 0; ch < NCH; ch++) {
        if (ch + 1 < NCH) cpwait1(); else cpwait0();
        __syncthreads();
        if (ch + 2 < NCH) issue(ch + 2, (ch + 2) % 3);

        const char* As = gsm + (ch % 3) * GEMM_STAGE_BYTES;
        const char* Bs = As + 12288;

#pragma unroll
        for (int kk = 0; kk < 2; kk++) {          // two k16 steps
            unsigned b0[4], b1[4];
#pragma unroll
            for (int nf = 0; nf < 4; nf++) {
                uint2 bv = *reinterpret_cast<const uint2*>(
                    Bs + (wn + nf * 8 + g) * 96 + kk * 32 + t * 8);
                b0[nf] = bv.x; b1[nf] = bv.y;
            }
#pragma unroll
            for (int mf = 0; mf < 4; mf++) {
                int r0 = wm + mf * 16 + g;
                uint2 a0v = *reinterpret_cast<const uint2*>(
                    As + r0 * 96 + kk * 32 + t * 8);
                uint2 a1v = *reinterpret_cast<const uint2*>(
                    As + (r0 + 8) * 96 + kk * 32 + t * 8);
#pragma unroll
                for (int nf = 0; nf < 4; nf++)
                    mma16(acc[mf][nf], a0v.x, a1v.x, a0v.y, a1v.y,
                          b0[nf], b1[nf]);
            }
        }
        // no trailing barrier: next iteration's sync provides the ordering
    }

#pragma unroll
    for (int mf = 0; mf < 4; mf++)
#pragma unroll
        for (int nf = 0; nf < 4; nf++)
#pragma unroll
            for (int c = 0; c < 4; c++) {
                int row = m0 + wm + mf * 16 + g + ((c >= 2) ? 8 : 0);
                int col = n0 + wn + nf * 8 + 2 * t + (c & 1);
                float v = acc[mf][nf][c] + bias[col];
                if (MODE == 0) {
                    int part = col >> 10, nn = col & 1023;
                    int hh = nn >> 6, e = nn & 63;
                    int bb = row >> 11, sq = row & 2047;
                    __half hv = __float2half_rn(v);
                    if (part == 0)
                        g_qb[(((size_t)(bb * HEADS + hh)) * SEQ + sq) * HD + e] = hv;
                    else if (part == 1)
                        g_kb[(((size_t)(bb * HEADS + hh)) * SEQ + sq) * HD + e] = hv;
                    else  // V stored TRANSPOSED [b,h,hd,s]
                        g_vb[(((size_t)(bb * HEADS + hh)) * HD + e) * SEQ + sq] = hv;
                } else {
                    C[(size_t)row * N + col] = v;
                }
            }
}

// ---------------- Flash attention (R13 version, unchanged) ----------------
// 256 threads (8 warps), 128-row q tile. CTA x=p handles tiles {p, 15-p}.
// K tile [64 kv][64 hd], V^T tile [64 hd][64 kv]: pitch 80 halves (160B,
// conflict-free LDS.64). P fp16 [128][pitch 80].
// Byte layout: K stage s at s*10240; V^T stage s at 20480+s*10240; P at 40960.
#define FA_SMEM_BYTES (40960 + 20480)   // 61440

__global__ __launch_bounds__(256)
void fa_kernel(const int* __restrict__ maskp)
{
    extern __shared__ char fsm[];
    char* Ps = fsm + 40960;

    const int tid = threadIdx.x, wid = tid >> 5, lane = tid & 31;
    const int g = lane >> 2, t = lane & 3;
    const int bh = blockIdx.y;
    const int causal = (maskp[0] != 0);

    const __half* kp  = g_kb + (size_t)bh * SEQ * HD;   // [s][hd]
    const __half* vtp = g_vb + (size_t)bh * HD * SEQ;   // [hd][s]
    const uint32_t fbase = s2u(fsm);
    const int wr = wid * 16;
    const int row0 = wr + g, row1 = wr + g + 8;
    const int b = bh >> 4, h = bh & 15;

    const int srow = (tid >> 2) & 63;
    const int sq0  = (tid & 3) * 2;

    for (int sub = 0; sub < 2; sub++) {
        const int Q = sub ? (15 - (int)blockIdx.x) : (int)blockIdx.x;
        const __half* qp = g_qb + ((size_t)bh * SEQ + Q * 128) * HD;

        unsigned qf[4][4];
#pragma unroll
        for (int kk = 0; kk < 4; kk++) {
            uint2 x0 = *reinterpret_cast<const uint2*>(&qp[(size_t)row0 * HD + kk * 16 + 4 * t]);
            uint2 x1 = *reinterpret_cast<const uint2*>(&qp[(size_t)row1 * HD + kk * 16 + 4 * t]);
            qf[kk][0] = x0.x; qf[kk][1] = x1.x;
            qf[kk][2] = x0.y; qf[kk][3] = x1.y;
        }

        float of[8][4];
#pragma unroll
        for (int nf = 0; nf < 8; nf++)
#pragma unroll
            for (int c = 0; c < 4; c++) of[nf][c] = 0.f;

        float m0 = -1e30f, m1 = -1e30f, l0 = 0.f, l1 = 0.f;
        const int grow0 = Q * 128 + row0, grow1 = Q * 128 + row1;

        const int jend = causal ? (2 * Q + 2) : (SEQ / 64);

        auto issuekv = [&](int j, int st) {
            const uint32_t kb = fbase + (uint32_t)st * 10240;
            const uint32_t vb = fbase + 20480u + (uint32_t)st * 10240;
#pragma unroll
            for (int i = 0; i < 2; i++) {
                int q = sq0 + i;
                uint32_t dofs = (uint32_t)(srow * 160 + q * 16);
                cpasync16(kb + dofs, &kp[((size_t)j * 64 + srow) * HD + q * 8]);
                cpasync16(vb + dofs, &vtp[(size_t)srow * SEQ + j * 64 + q * 8]);
            }
            cpcommit();
        };

        issuekv(0, 0);

        for (int j = 0; j < jend; j++) {
            const int cur = j & 1;
            if (j + 1 < jend) { issuekv(j + 1, cur ^ 1); cpwait1(); }
            else { cpwait0(); }
            __syncthreads();

            const char* Ks = fsm + cur * 10240;
            const char* Vt = fsm + 20480 + cur * 10240;

            // S = Q K^T
            float sf[8][4];
#pragma unroll
            for (int nf = 0; nf < 8; nf++)
#pragma unroll
                for (int c = 0; c < 4; c++) sf[nf][c] = 0.f;
#pragma unroll
            for (int kk = 0; kk < 4; kk++) {
#pragma unroll
                for (int nf = 0; nf < 8; nf++) {
                    uint2 bv = *reinterpret_cast<const uint2*>(
                        Ks + (nf * 8 + g) * 160 + kk * 32 + t * 8);
                    mma16(sf[nf], qf[kk][0], qf[kk][1], qf[kk][2], qf[kk][3],
                          bv.x, bv.y);
                }
            }

            // scale + causal mask
            const bool mk = causal && (j >= 2 * Q);
            const int jc = j * 64;
#pragma unroll
            for (int nf = 0; nf < 8; nf++) {
                int c0 = jc + nf * 8 + 2 * t, c1 = c0 + 1;
                sf[nf][0] = (mk && c0 > grow0) ? -1e30f : sf[nf][0] * 0.125f;
                sf[nf][1] = (mk && c1 > grow0) ? -1e30f : sf[nf][1] * 0.125f;
                sf[nf][2] = (mk && c0 > grow1) ? -1e30f : sf[nf][2] * 0.125f;
                sf[nf][3] = (mk && c1 > grow1) ? -1e30f : sf[nf][3] * 0.125f;
            }

            // register softmax across the t-quad
            float mx0 = -1e30f, mx1 = -1e30f;
#pragma unroll
            for (int nf = 0; nf < 8; nf++) {
                mx0 = fmaxf(mx0, fmaxf(sf[nf][0], sf[nf][1]));
                mx1 = fmaxf(mx1, fmaxf(sf[nf][2], sf[nf][3]));
            }
            mx0 = fmaxf(mx0, __shfl_xor_sync(0xffffffffu, mx0, 1));
            mx0 = fmaxf(mx0, __shfl_xor_sync(0xffffffffu, mx0, 2));
            mx1 = fmaxf(mx1, __shfl_xor_sync(0xffffffffu, mx1, 1));
            mx1 = fmaxf(mx1, __shfl_xor_sync(0xffffffffu, mx1, 2));
            const float nm0 = fmaxf(m0, mx0), nm1 = fmaxf(m1, mx1);

            float sum0 = 0.f, sum1 = 0.f;
#pragma unroll
            for (int nf = 0; nf < 8; nf++) {
                sf[nf][0] = __expf(sf[nf][0] - nm0);
                sf[nf][1] = __expf(sf[nf][1] - nm0);
                sf[nf][2] = __expf(sf[nf][2] - nm1);
                sf[nf][3] = __expf(sf[nf][3] - nm1);
                sum0 += sf[nf][0] + sf[nf][1];
                sum1 += sf[nf][2] + sf[nf][3];
            }
            sum0 += __shfl_xor_sync(0xffffffffu, sum0, 1);
            sum0 += __shfl_xor_sync(0xffffffffu, sum0, 2);
            sum1 += __shfl_xor_sync(0xffffffffu, sum1, 1);
            sum1 += __shfl_xor_sync(0xffffffffu, sum1, 2);

            const float sc0 = __expf(m0 - nm0), sc1 = __expf(m1 - nm1);
            l0 = l0 * sc0 + sum0; l1 = l1 * sc1 + sum1;
            m0 = nm0; m1 = nm1;

            // P (fp16) to its own buffer (warp-local rows)
#pragma unroll
            for (int nf = 0; nf < 8; nf++) {
                *reinterpret_cast<unsigned*>(Ps + row0 * 160 + nf * 16 + t * 4)
                    = pack2(sf[nf][0], sf[nf][1]);
                *reinterpret_cast<unsigned*>(Ps + row1 * 160 + nf * 16 + t * 4)
                    = pack2(sf[nf][2], sf[nf][3]);
            }
            __syncwarp();   // PV A-fragments read only this warp's 16 rows

            // rescale O, then O += P V  (A=P m16k16 over kv, B=V^T)
#pragma unroll
            for (int nf = 0; nf < 8; nf++) {
                of[nf][0] *= sc0; of[nf][1] *= sc0; of[nf][2] *= sc1; of[nf][3] *= sc1;
            }
#pragma unroll
            for (int kk = 0; kk < 4; kk++) {
                uint2 p0 = *reinterpret_cast<const uint2*>(Ps + row0 * 160 + kk * 32 + t * 8);
                uint2 p1 = *reinterpret_cast<const uint2*>(Ps + row1 * 160 + kk * 32 + t * 8);
#pragma unroll
                for (int nf = 0; nf < 8; nf++) {
                    uint2 bv = *reinterpret_cast<const uint2*>(
                        Vt + (nf * 8 + g) * 160 + kk * 32 + t * 8);
                    mma16(of[nf], p0.x, p1.x, p0.y, p1.y, bv.x, bv.y);
                }
            }
            __syncthreads();   // Ks/Vt reads done before next issue overwrites
        }

        // normalize and write g_ab fp16 [b, s, h, hd]
        const float il0 = 1.f / l0, il1 = 1.f / l1;
        const int q0 = Q * 128 + row0, q1 = Q * 128 + row1;
#pragma unroll
        for (int nf = 0; nf < 8; nf++) {
            int col = nf * 8 + 2 * t;
            *reinterpret_cast<unsigned*>(
                &g_ab[(((size_t)b * SEQ + q0) * HEADS + h) * HD + col])
                = pack2(of[nf][0] * il0, of[nf][1] * il0);
            *reinterpret_cast<unsigned*>(
                &g_ab[(((size_t)b * SEQ + q1) * HEADS + h) * HD + col])
                = pack2(of[nf][2] * il1, of[nf][3] * il1);
        }
    }
}

// ---------------- launch ----------------
extern "C" void kernel_launch(void* const* d_in, const int* in_sizes, int n_in,
                              void* d_out, int out_size)
{
    const float* x    = (const float*)d_in[0];
    const float* Wqkv = (const float*)d_in[1];
    const float* bqkv = (const float*)d_in[2];
    const float* Wd   = (const float*)d_in[3];
    const float* bd   = (const float*)d_in[4];
    const int*   mask = (const int*)d_in[5];
    float* out = (float*)d_out;

    cudaFuncSetAttribute(gemm_kernel<0>, cudaFuncAttributeMaxDynamicSharedMemorySize, GEMM_SMEM_BYTES);
    cudaFuncSetAttribute(gemm_kernel<1>, cudaFuncAttributeMaxDynamicSharedMemorySize, GEMM_SMEM_BYTES);
    cudaFuncSetAttribute(fa_kernel,      cudaFuncAttributeMaxDynamicSharedMemorySize, FA_SMEM_BYTES);

    static __half* wq_dev = nullptr;
    static __half* wd_dev = nullptr;
    if (!wq_dev) {
        cudaGetSymbolAddress((void**)&wq_dev, g_wqh);
        cudaGetSymbolAddress((void**)&wd_dev, g_wdh);
    }

    convert_kernel<<<1024, 256>>>(x, Wqkv, Wd);

    gemm_kernel<0><<<dim3(N_QKV / 128, MTOT / 128), 256, GEMM_SMEM_BYTES>>>(
        wq_dev, bqkv, nullptr, MTOT, N_QKV, DMODEL);

    fa_kernel<<<dim3(8, NB * HEADS), 256, FA_SMEM_BYTES>>>(mask);

    gemm_kernel<1><<<dim3(DMODEL / 128, MTOT / 128), 256, GEMM_SMEM_BYTES>>>(
        wd_dev, bd, out, MTOT, DMODEL, DMODEL);
}